// round 15
// baseline (speedup 1.0000x reference)
#include <cuda_runtime.h>

// ---------------- problem constants ----------------
#define MTOT 65536
#define EF   256
#define HF   256
#define LF   1024
#define NBLK 6
#define TLEN 2048
#define BB   32
#define NC   16
#define TC   128

// ---------------- scratch (device globals) ----------------
static __device__ float g_y[(size_t)MTOT * EF];
static __device__ float g_x[(size_t)MTOT * EF];
static __device__ float g_bure[(size_t)MTOT * HF];
static __device__ float g_buim[(size_t)MTOT * HF];
static __device__ float g_hre[(size_t)MTOT * HF];
static __device__ float g_him[(size_t)MTOT * HF];
static __device__ float g_u[(size_t)MTOT * EF];
static __device__ float g_g[(size_t)MTOT * (LF / 2)];
static __device__ float g_part[512 * 512];
static __device__ float g_bna[EF], g_bnc[EF];
static __device__ float g_lr[HF], g_li[HF], g_gam[HF];
static __device__ float g_l8r[HF], g_l8i[HF];
static __device__ float g_L128r[HF], g_L128i[HF];
static __device__ float g_car_re[BB * NC * HF], g_car_im[BB * NC * HF];

// ======== fused BN finalize (blocks 0..255) + lambda precompute (block 256) ========
__global__ void __launch_bounds__(256) bn_lam(const float* __restrict__ scale,
                                              const float* __restrict__ bias,
                                              const float* __restrict__ nul,
                                              const float* __restrict__ thl) {
    if (blockIdx.x == 256) {
        int h = threadIdx.x;
        float nu = expf(nul[h]);
        float th = expf(thl[h]);
        float r = expf(-nu);
        float sn, cs;
        sincosf(th, &sn, &cs);
        float lr = r * cs, li = r * sn;
        g_lr[h] = lr;
        g_li[h] = li;
        g_gam[h] = sqrtf(fmaxf(1.0f - r * r, 1e-12f));
        float ar = lr, ai = li;
#pragma unroll
        for (int s = 0; s < 3; s++) {        // lam^8
            float nr = ar * ar - ai * ai;
            float ni = 2.0f * ar * ai;
            ar = nr;
            ai = ni;
        }
        g_l8r[h] = ar;
        g_l8i[h] = ai;
#pragma unroll
        for (int s = 0; s < 4; s++) {        // lam^128
            float nr = ar * ar - ai * ai;
            float ni = 2.0f * ar * ai;
            ar = nr;
            ai = ni;
        }
        g_L128r[h] = ar;
        g_L128i[h] = ai;
        return;
    }
    __shared__ float sm1[256], sm2[256];
    int e = blockIdx.x;
    int t = threadIdx.x;
    float s = g_part[t * 512 + e] + g_part[(t + 256) * 512 + e];
    float s2 = g_part[t * 512 + 256 + e] + g_part[(t + 256) * 512 + 256 + e];
    sm1[t] = s;
    sm2[t] = s2;
    __syncthreads();
    for (int st = 128; st > 0; st >>= 1) {
        if (t < st) {
            sm1[t] += sm1[t + st];
            sm2[t] += sm2[t + st];
        }
        __syncthreads();
    }
    if (t == 0) {
        const float inv = 1.0f / 65536.0f;
        float mu = sm1[0] * inv;
        float var = fmaxf(sm2[0] * inv - mu * mu, 0.0f);
        float a = rsqrtf(var + 1e-5f) * scale[e];
        g_bna[e] = a;
        g_bnc[e] = bias[e] - mu * a;
    }
}

// ================= GEMM: (bure,buim) = BN(x) @ [Bre^T, Bim^T] * gamma  (fused dual-B TN)
//   KC=16 champion; epilogue computes per-chunk scan carries ==========================
__global__ void __launch_bounds__(256) gemm_bu2(int xsel, const float* __restrict__ Wr,
                                                const float* __restrict__ Wi) {
    const float* A = xsel ? g_x : g_y;
    __shared__ __align__(16) float As[16][128];
    __shared__ __align__(16) float Bsr[16][64];
    __shared__ __align__(16) float Bsi[16][64];
    const int tid = threadIdx.x;
    const int m0 = blockIdx.x * 128;
    const int n0 = blockIdx.y * 64;
    const int tx = tid & 15;
    const int ty = tid >> 4;
    const int lr = tid >> 2;
    const int lk = (tid & 3) * 4;
    float accr[8][4], acci[8][4];
#pragma unroll
    for (int j = 0; j < 8; j++)
#pragma unroll
        for (int i = 0; i < 4; i++) { accr[j][i] = 0.f; acci[j][i] = 0.f; }

    for (int k0 = 0; k0 < 256; k0 += 16) {
        float4 a0 = *(const float4*)(A + (size_t)(m0 + lr) * 256 + k0 + lk);
        float4 a1 = *(const float4*)(A + (size_t)(m0 + lr + 64) * 256 + k0 + lk);
        float4 wr = *(const float4*)(Wr + (size_t)(n0 + lr) * 256 + k0 + lk);
        float4 wi = *(const float4*)(Wi + (size_t)(n0 + lr) * 256 + k0 + lk);
        float4 ba = *(const float4*)(g_bna + k0 + lk);
        float4 bc = *(const float4*)(g_bnc + k0 + lk);
        a0.x = fmaf(ba.x, a0.x, bc.x); a0.y = fmaf(ba.y, a0.y, bc.y);
        a0.z = fmaf(ba.z, a0.z, bc.z); a0.w = fmaf(ba.w, a0.w, bc.w);
        a1.x = fmaf(ba.x, a1.x, bc.x); a1.y = fmaf(ba.y, a1.y, bc.y);
        a1.z = fmaf(ba.z, a1.z, bc.z); a1.w = fmaf(ba.w, a1.w, bc.w);
        __syncthreads();
        As[lk + 0][lr] = a0.x; As[lk + 1][lr] = a0.y; As[lk + 2][lr] = a0.z; As[lk + 3][lr] = a0.w;
        As[lk + 0][lr + 64] = a1.x; As[lk + 1][lr + 64] = a1.y;
        As[lk + 2][lr + 64] = a1.z; As[lk + 3][lr + 64] = a1.w;
        Bsr[lk + 0][lr] = wr.x; Bsr[lk + 1][lr] = wr.y; Bsr[lk + 2][lr] = wr.z; Bsr[lk + 3][lr] = wr.w;
        Bsi[lk + 0][lr] = wi.x; Bsi[lk + 1][lr] = wi.y; Bsi[lk + 2][lr] = wi.z; Bsi[lk + 3][lr] = wi.w;
        __syncthreads();
#pragma unroll
        for (int kk = 0; kk < 16; kk++) {
            float4 av0 = *(const float4*)&As[kk][ty * 8];
            float4 av1 = *(const float4*)&As[kk][ty * 8 + 4];
            float4 br = *(const float4*)&Bsr[kk][tx * 4];
            float4 bi = *(const float4*)&Bsi[kk][tx * 4];
            float a[8] = {av0.x, av0.y, av0.z, av0.w, av1.x, av1.y, av1.z, av1.w};
            float brv[4] = {br.x, br.y, br.z, br.w};
            float biv[4] = {bi.x, bi.y, bi.z, bi.w};
#pragma unroll
            for (int j = 0; j < 8; j++)
#pragma unroll
                for (int i = 0; i < 4; i++) {
                    accr[j][i] = fmaf(a[j], brv[i], accr[j][i]);
                    acci[j][i] = fmaf(a[j], biv[i], acci[j][i]);
                }
        }
    }
    float4 gm = *(const float4*)(g_gam + n0 + tx * 4);
    float sr[4] = {0.f, 0.f, 0.f, 0.f}, si[4] = {0.f, 0.f, 0.f, 0.f};
    float lrv[4], liv[4];
#pragma unroll
    for (int i = 0; i < 4; i++) {
        lrv[i] = g_lr[n0 + tx * 4 + i];
        liv[i] = g_li[n0 + tx * 4 + i];
    }
#pragma unroll
    for (int j = 0; j < 8; j++) {
        size_t row = (size_t)(m0 + ty * 8 + j);
        float ur[4], ui[4];
        ur[0] = accr[j][0] * gm.x; ur[1] = accr[j][1] * gm.y;
        ur[2] = accr[j][2] * gm.z; ur[3] = accr[j][3] * gm.w;
        ui[0] = acci[j][0] * gm.x; ui[1] = acci[j][1] * gm.y;
        ui[2] = acci[j][2] * gm.z; ui[3] = acci[j][3] * gm.w;
        *(float4*)(g_bure + row * 256 + n0 + tx * 4) = make_float4(ur[0], ur[1], ur[2], ur[3]);
        *(float4*)(g_buim + row * 256 + n0 + tx * 4) = make_float4(ui[0], ui[1], ui[2], ui[3]);
#pragma unroll
        for (int i = 0; i < 4; i++) {
            float nr = fmaf(lrv[i], sr[i], fmaf(-liv[i], si[i], ur[i]));
            float ni = fmaf(lrv[i], si[i], fmaf(liv[i], sr[i], ui[i]));
            sr[i] = nr;
            si[i] = ni;
        }
    }
    __syncthreads();
#pragma unroll
    for (int i = 0; i < 4; i++) {
        As[ty][tx * 4 + i] = sr[i];
        As[ty][64 + tx * 4 + i] = si[i];
    }
    __syncthreads();
    if (tid < 64) {
        int col = tid;
        int n = n0 + col;
        float l8r = g_l8r[n], l8i = g_l8i[n];
        float Hr = 0.f, Hi = 0.f;
#pragma unroll
        for (int gI = 0; gI < 16; gI++) {
            float ur = As[gI][col], ui = As[gI][64 + col];
            float nr = fmaf(l8r, Hr, fmaf(-l8i, Hi, ur));
            float ni = fmaf(l8r, Hi, fmaf(l8i, Hr, ui));
            Hr = nr;
            Hi = ni;
        }
        int b = m0 >> 11;
        int cch = (m0 >> 7) & 15;
        int ci = (b * NC + cch) * HF + n;
        g_car_re[ci] = Hr;
        g_car_im[ci] = Hi;
    }
}

// ===== scan final: 4 h-columns per thread (float4), 4 chunks per CTA, prefix recompute ===
__global__ void __launch_bounds__(256) scan_final4() {
    const int tid = threadIdx.x;
    const int hq = (tid & 63) * 4;          // h column group
    const int cloc = tid >> 6;              // 0..3
    const int b = blockIdx.x >> 2;
    const int c = (blockIdx.x & 3) * 4 + cloc;
    float4 lr4 = *(const float4*)(g_lr + hq);
    float4 li4 = *(const float4*)(g_li + hq);
    float4 Lr4 = *(const float4*)(g_L128r + hq);
    float4 Li4 = *(const float4*)(g_L128i + hq);
    float lr[4] = {lr4.x, lr4.y, lr4.z, lr4.w};
    float li[4] = {li4.x, li4.y, li4.z, li4.w};
    float Lr[4] = {Lr4.x, Lr4.y, Lr4.z, Lr4.w};
    float Li[4] = {Li4.x, Li4.y, Li4.z, Li4.w};
    float hr[4] = {0.f, 0.f, 0.f, 0.f}, hi[4] = {0.f, 0.f, 0.f, 0.f};
    // prefix from chunk carries 0..c-1 (identical order to reference prefix)
    for (int j = 0; j < c; j++) {
        const float4 cr4 = *(const float4*)(g_car_re + (b * NC + j) * HF + hq);
        const float4 ci4 = *(const float4*)(g_car_im + (b * NC + j) * HF + hq);
        float cr[4] = {cr4.x, cr4.y, cr4.z, cr4.w};
        float ci[4] = {ci4.x, ci4.y, ci4.z, ci4.w};
#pragma unroll
        for (int i = 0; i < 4; i++) {
            float nr = fmaf(Lr[i], hr[i], fmaf(-Li[i], hi[i], cr[i]));
            float ni = fmaf(Lr[i], hi[i], fmaf(Li[i], hr[i], ci[i]));
            hr[i] = nr;
            hi[i] = ni;
        }
    }
    size_t base = ((size_t)b * TLEN + c * TC) * HF + hq;
#pragma unroll 2
    for (int t = 0; t < TC; t++) {
        size_t idx = base + (size_t)t * HF;
        float4 ur4 = *(const float4*)(g_bure + idx);
        float4 ui4 = *(const float4*)(g_buim + idx);
        float ur[4] = {ur4.x, ur4.y, ur4.z, ur4.w};
        float ui[4] = {ui4.x, ui4.y, ui4.z, ui4.w};
#pragma unroll
        for (int i = 0; i < 4; i++) {
            float nr = fmaf(lr[i], hr[i], fmaf(-li[i], hi[i], ur[i]));
            float ni = fmaf(lr[i], hi[i], fmaf(li[i], hr[i], ui[i]));
            hr[i] = nr;
            hi[i] = ni;
        }
        *(float4*)(g_hre + idx) = make_float4(hr[0], hr[1], hr[2], hr[3]);
        *(float4*)(g_him + idx) = make_float4(hi[0], hi[1], hi[2], hi[3]);
    }
}

// ================= GEMM: u = Re(hs @ Cc) + D*BN(x)  (dual TN, wide N=128, KC=16) =========
__global__ void __launch_bounds__(256) gemm_cproj(const float* __restrict__ Wr,
                                                  const float* __restrict__ Wi,
                                                  const float* __restrict__ Dv, int xsel) {
    const float* Xin = xsel ? g_x : g_y;
    __shared__ __align__(16) float Asr[16][128];
    __shared__ __align__(16) float Asi[16][128];
    __shared__ __align__(16) float Bsr[16][128];
    __shared__ __align__(16) float Bsi[16][128];
    const int tid = threadIdx.x;
    const int m0 = blockIdx.x * 128;
    const int n0 = blockIdx.y * 128;
    const int tx = tid & 15;
    const int ty = tid >> 4;
    const int lr = tid >> 2;
    const int lk = (tid & 3) * 4;
    float acc[8][2][4];
#pragma unroll
    for (int j = 0; j < 8; j++)
#pragma unroll
        for (int g = 0; g < 2; g++)
#pragma unroll
            for (int i = 0; i < 4; i++) acc[j][g][i] = 0.f;

    for (int k0 = 0; k0 < 256; k0 += 16) {
        float4 ar0 = *(const float4*)(g_hre + (size_t)(m0 + lr) * 256 + k0 + lk);
        float4 ar1 = *(const float4*)(g_hre + (size_t)(m0 + lr + 64) * 256 + k0 + lk);
        float4 ai0 = *(const float4*)(g_him + (size_t)(m0 + lr) * 256 + k0 + lk);
        float4 ai1 = *(const float4*)(g_him + (size_t)(m0 + lr + 64) * 256 + k0 + lk);
        float4 wr0 = *(const float4*)(Wr + (size_t)(n0 + lr) * 256 + k0 + lk);
        float4 wr1 = *(const float4*)(Wr + (size_t)(n0 + lr + 64) * 256 + k0 + lk);
        float4 wi0 = *(const float4*)(Wi + (size_t)(n0 + lr) * 256 + k0 + lk);
        float4 wi1 = *(const float4*)(Wi + (size_t)(n0 + lr + 64) * 256 + k0 + lk);
        __syncthreads();
        Asr[lk + 0][lr] = ar0.x; Asr[lk + 1][lr] = ar0.y; Asr[lk + 2][lr] = ar0.z; Asr[lk + 3][lr] = ar0.w;
        Asr[lk + 0][lr + 64] = ar1.x; Asr[lk + 1][lr + 64] = ar1.y;
        Asr[lk + 2][lr + 64] = ar1.z; Asr[lk + 3][lr + 64] = ar1.w;
        Asi[lk + 0][lr] = ai0.x; Asi[lk + 1][lr] = ai0.y; Asi[lk + 2][lr] = ai0.z; Asi[lk + 3][lr] = ai0.w;
        Asi[lk + 0][lr + 64] = ai1.x; Asi[lk + 1][lr + 64] = ai1.y;
        Asi[lk + 2][lr + 64] = ai1.z; Asi[lk + 3][lr + 64] = ai1.w;
        Bsr[lk + 0][lr] = wr0.x; Bsr[lk + 1][lr] = wr0.y; Bsr[lk + 2][lr] = wr0.z; Bsr[lk + 3][lr] = wr0.w;
        Bsr[lk + 0][lr + 64] = wr1.x; Bsr[lk + 1][lr + 64] = wr1.y;
        Bsr[lk + 2][lr + 64] = wr1.z; Bsr[lk + 3][lr + 64] = wr1.w;
        Bsi[lk + 0][lr] = wi0.x; Bsi[lk + 1][lr] = wi0.y; Bsi[lk + 2][lr] = wi0.z; Bsi[lk + 3][lr] = wi0.w;
        Bsi[lk + 0][lr + 64] = wi1.x; Bsi[lk + 1][lr + 64] = wi1.y;
        Bsi[lk + 2][lr + 64] = wi1.z; Bsi[lk + 3][lr + 64] = wi1.w;
        __syncthreads();
#pragma unroll
        for (int kk = 0; kk < 16; kk++) {
            float4 r0 = *(const float4*)&Asr[kk][ty * 8];
            float4 r1 = *(const float4*)&Asr[kk][ty * 8 + 4];
            float4 i0 = *(const float4*)&Asi[kk][ty * 8];
            float4 i1 = *(const float4*)&Asi[kk][ty * 8 + 4];
            float4 br0 = *(const float4*)&Bsr[kk][tx * 4];
            float4 br1 = *(const float4*)&Bsr[kk][tx * 4 + 64];
            float4 bi0 = *(const float4*)&Bsi[kk][tx * 4];
            float4 bi1 = *(const float4*)&Bsi[kk][tx * 4 + 64];
            float arv[8] = {r0.x, r0.y, r0.z, r0.w, r1.x, r1.y, r1.z, r1.w};
            float aiv[8] = {i0.x, i0.y, i0.z, i0.w, i1.x, i1.y, i1.z, i1.w};
            float brv[2][4] = {{br0.x, br0.y, br0.z, br0.w}, {br1.x, br1.y, br1.z, br1.w}};
            float biv[2][4] = {{bi0.x, bi0.y, bi0.z, bi0.w}, {bi1.x, bi1.y, bi1.z, bi1.w}};
#pragma unroll
            for (int j = 0; j < 8; j++)
#pragma unroll
                for (int g = 0; g < 2; g++)
#pragma unroll
                    for (int i = 0; i < 4; i++) {
                        acc[j][g][i] = fmaf(arv[j], brv[g][i], acc[j][g][i]);
                        acc[j][g][i] = fmaf(-aiv[j], biv[g][i], acc[j][g][i]);
                    }
        }
    }
#pragma unroll
    for (int g = 0; g < 2; g++) {
        int n = n0 + g * 64 + tx * 4;
        float4 dq = *(const float4*)(Dv + n);
        float4 ba = *(const float4*)(g_bna + n);
        float4 bc = *(const float4*)(g_bnc + n);
#pragma unroll
        for (int j = 0; j < 8; j++) {
            size_t row = (size_t)(m0 + ty * 8 + j);
            float4 xv = *(const float4*)(Xin + row * 256 + n);
            float4 o;
            o.x = acc[j][g][0] + dq.x * fmaf(ba.x, xv.x, bc.x);
            o.y = acc[j][g][1] + dq.y * fmaf(ba.y, xv.y, bc.y);
            o.z = acc[j][g][2] + dq.z * fmaf(ba.z, xv.z, bc.z);
            o.w = acc[j][g][3] + dq.w * fmaf(ba.w, xv.w, bc.w);
            *(float4*)(g_u + row * 256 + n) = o;
        }
    }
}

// ================= GEMM: g = GLU(u @ W1 + b1)   (NN, dual-B tile, KC=16) =================
__global__ void __launch_bounds__(256) gemm_glu(const float* __restrict__ W1,
                                                const float* __restrict__ b1) {
    __shared__ __align__(16) float As[16][128];
    __shared__ __align__(16) float Ba[16][64];
    __shared__ __align__(16) float Bb[16][64];
    const int tid = threadIdx.x;
    const int m0 = blockIdx.x * 128;
    const int n0 = blockIdx.y * 64;
    const int tx = tid & 15;
    const int ty = tid >> 4;
    const int lr = tid >> 2;
    const int lk = (tid & 3) * 4;
    const int bk = tid >> 4;
    const int bn = (tid & 15) * 4;
    float acca[8][4], accb[8][4];
#pragma unroll
    for (int j = 0; j < 8; j++)
#pragma unroll
        for (int i = 0; i < 4; i++) { acca[j][i] = 0.f; accb[j][i] = 0.f; }

    for (int k0 = 0; k0 < 256; k0 += 16) {
        float4 a0 = *(const float4*)(g_u + (size_t)(m0 + lr) * 256 + k0 + lk);
        float4 a1 = *(const float4*)(g_u + (size_t)(m0 + lr + 64) * 256 + k0 + lk);
        float4 wa = *(const float4*)(W1 + (size_t)(k0 + bk) * 1024 + n0 + bn);
        float4 wb = *(const float4*)(W1 + (size_t)(k0 + bk) * 1024 + 512 + n0 + bn);
        __syncthreads();
        As[lk + 0][lr] = a0.x; As[lk + 1][lr] = a0.y; As[lk + 2][lr] = a0.z; As[lk + 3][lr] = a0.w;
        As[lk + 0][lr + 64] = a1.x; As[lk + 1][lr + 64] = a1.y;
        As[lk + 2][lr + 64] = a1.z; As[lk + 3][lr + 64] = a1.w;
        *(float4*)&Ba[bk][bn] = wa;
        *(float4*)&Bb[bk][bn] = wb;
        __syncthreads();
#pragma unroll
        for (int kk = 0; kk < 16; kk++) {
            float4 av0 = *(const float4*)&As[kk][ty * 8];
            float4 av1 = *(const float4*)&As[kk][ty * 8 + 4];
            float4 bva = *(const float4*)&Ba[kk][tx * 4];
            float4 bvb = *(const float4*)&Bb[kk][tx * 4];
            float a[8] = {av0.x, av0.y, av0.z, av0.w, av1.x, av1.y, av1.z, av1.w};
            float ba_[4] = {bva.x, bva.y, bva.z, bva.w};
            float bb_[4] = {bvb.x, bvb.y, bvb.z, bvb.w};
#pragma unroll
            for (int j = 0; j < 8; j++)
#pragma unroll
                for (int i = 0; i < 4; i++) {
                    acca[j][i] = fmaf(a[j], ba_[i], acca[j][i]);
                    accb[j][i] = fmaf(a[j], bb_[i], accb[j][i]);
                }
        }
    }
    float4 b1a = *(const float4*)(b1 + n0 + tx * 4);
    float4 b1b = *(const float4*)(b1 + 512 + n0 + tx * 4);
#pragma unroll
    for (int j = 0; j < 8; j++) {
        float za[4], zb[4];
        za[0] = acca[j][0] + b1a.x; za[1] = acca[j][1] + b1a.y;
        za[2] = acca[j][2] + b1a.z; za[3] = acca[j][3] + b1a.w;
        zb[0] = accb[j][0] + b1b.x; zb[1] = accb[j][1] + b1b.y;
        zb[2] = accb[j][2] + b1b.z; zb[3] = accb[j][3] + b1b.w;
        float4 o;
        o.x = __fdividef(za[0], 1.0f + __expf(-zb[0]));
        o.y = __fdividef(za[1], 1.0f + __expf(-zb[1]));
        o.z = __fdividef(za[2], 1.0f + __expf(-zb[2]));
        o.w = __fdividef(za[3], 1.0f + __expf(-zb[3]));
        *(float4*)(g_g + (size_t)(m0 + ty * 8 + j) * 512 + n0 + tx * 4) = o;
    }
}

// ================= GEMM NN wide (encoder ROLE=0, MLP2+residual ROLE=1; N=128, KC=16) =====
template <int ROLE>
__global__ void __launch_bounds__(256) gemm_nn(const float* __restrict__ Aext, int K,
                                               const float* __restrict__ B,
                                               const float* __restrict__ bias) {
    const float* A = (ROLE == 0) ? Aext : g_g;
    float* out = (ROLE == 0) ? g_y : g_x;
    __shared__ __align__(16) float As[16][128];
    __shared__ __align__(16) float Bs[16][128];
    const int tid = threadIdx.x;
    const int m0 = blockIdx.x * 128;
    const int n0 = blockIdx.y * 128;
    const int tx = tid & 15;
    const int ty = tid >> 4;
    const int lr = tid >> 2;
    const int lk = (tid & 3) * 4;
    const int bk = tid >> 4;
    const int bn = (tid & 15) * 4;
    float acc[8][2][4];
#pragma unroll
    for (int j = 0; j < 8; j++)
#pragma unroll
        for (int g = 0; g < 2; g++)
#pragma unroll
            for (int i = 0; i < 4; i++) acc[j][g][i] = 0.f;

    for (int k0 = 0; k0 < K; k0 += 16) {
        float4 a0 = *(const float4*)(A + (size_t)(m0 + lr) * K + k0 + lk);
        float4 a1 = *(const float4*)(A + (size_t)(m0 + lr + 64) * K + k0 + lk);
        float4 wv0 = *(const float4*)(B + (size_t)(k0 + bk) * 256 + n0 + bn);
        float4 wv1 = *(const float4*)(B + (size_t)(k0 + bk) * 256 + n0 + 64 + bn);
        __syncthreads();
        As[lk + 0][lr] = a0.x; As[lk + 1][lr] = a0.y; As[lk + 2][lr] = a0.z; As[lk + 3][lr] = a0.w;
        As[lk + 0][lr + 64] = a1.x; As[lk + 1][lr + 64] = a1.y;
        As[lk + 2][lr + 64] = a1.z; As[lk + 3][lr + 64] = a1.w;
        *(float4*)&Bs[bk][bn] = wv0;
        *(float4*)&Bs[bk][bn + 64] = wv1;
        __syncthreads();
#pragma unroll
        for (int kk = 0; kk < 16; kk++) {
            float4 av0 = *(const float4*)&As[kk][ty * 8];
            float4 av1 = *(const float4*)&As[kk][ty * 8 + 4];
            float4 bv0 = *(const float4*)&Bs[kk][tx * 4];
            float4 bv1 = *(const float4*)&Bs[kk][tx * 4 + 64];
            float a[8] = {av0.x, av0.y, av0.z, av0.w, av1.x, av1.y, av1.z, av1.w};
            float bv[2][4] = {{bv0.x, bv0.y, bv0.z, bv0.w}, {bv1.x, bv1.y, bv1.z, bv1.w}};
#pragma unroll
            for (int j = 0; j < 8; j++)
#pragma unroll
                for (int g = 0; g < 2; g++)
#pragma unroll
                    for (int i = 0; i < 4; i++)
                        acc[j][g][i] = fmaf(a[j], bv[g][i], acc[j][g][i]);
        }
    }

    float ls[2][4], ls2[2][4];
#pragma unroll
    for (int g = 0; g < 2; g++)
#pragma unroll
        for (int i = 0; i < 4; i++) { ls[g][i] = 0.f; ls2[g][i] = 0.f; }
#pragma unroll
    for (int g = 0; g < 2; g++) {
        int n = n0 + g * 64 + tx * 4;
        float4 bq = *(const float4*)(bias + n);
#pragma unroll
        for (int j = 0; j < 8; j++) {
            size_t row = (size_t)(m0 + ty * 8 + j);
            float4 o;
            o.x = acc[j][g][0] + bq.x; o.y = acc[j][g][1] + bq.y;
            o.z = acc[j][g][2] + bq.z; o.w = acc[j][g][3] + bq.w;
            if (ROLE == 1) {
                float4 yv = *(const float4*)(g_y + row * 256 + n);
                o.x += yv.x; o.y += yv.y; o.z += yv.z; o.w += yv.w;
            }
            ls[g][0] += o.x; ls[g][1] += o.y; ls[g][2] += o.z; ls[g][3] += o.w;
            ls2[g][0] += o.x * o.x; ls2[g][1] += o.y * o.y;
            ls2[g][2] += o.z * o.z; ls2[g][3] += o.w * o.w;
            *(float4*)(out + row * 256 + n) = o;
        }
    }

    float* red = &As[0][0];
    __syncthreads();
#pragma unroll
    for (int g = 0; g < 2; g++)
#pragma unroll
        for (int i = 0; i < 4; i++) red[tid * 8 + g * 4 + i] = ls[g][i];
    __syncthreads();
    float sv = 0.f;
    if (tid < 128) {
        int g = tid >> 6, txr = (tid >> 2) & 15, ir = tid & 3;
#pragma unroll
        for (int k = 0; k < 16; k++) sv += red[(k * 16 + txr) * 8 + g * 4 + ir];
    }
    __syncthreads();
#pragma unroll
    for (int g = 0; g < 2; g++)
#pragma unroll
        for (int i = 0; i < 4; i++) red[tid * 8 + g * 4 + i] = ls2[g][i];
    __syncthreads();
    if (tid < 128) {
        int g = tid >> 6, txr = (tid >> 2) & 15, ir = tid & 3;
        float s2 = 0.f;
#pragma unroll
        for (int k = 0; k < 16; k++) s2 += red[(k * 16 + txr) * 8 + g * 4 + ir];
        int col = n0 + g * 64 + txr * 4 + ir;
        g_part[blockIdx.x * 512 + col] = sv;
        g_part[blockIdx.x * 512 + 256 + col] = s2;
    }
}

// ================= fused mean-pool + head =================
__global__ void __launch_bounds__(256) pool_head(const float* __restrict__ Wout,
                                                 const float* __restrict__ bout,
                                                 float* __restrict__ out) {
    __shared__ float pooled[256];
    int b = blockIdx.x;
    int e = threadIdx.x;
    float s = 0.f;
#pragma unroll
    for (int k = 0; k < 16; k++) s += g_part[(b * 16 + k) * 512 + e];
    pooled[e] = s * (1.0f / (float)TLEN);
    __syncthreads();
    if (e < 10) {
        float acc = bout[e];
        for (int q = 0; q < 256; q++) acc = fmaf(pooled[q], Wout[q * 10 + e], acc);
        out[b * 10 + e] = acc;
    }
}

// ================= host orchestration =================
extern "C" void kernel_launch(void* const* d_in, const int* in_sizes, int n_in,
                              void* d_out, int out_size) {
    const float* x    = (const float*)d_in[0];
    const float* Wenc = (const float*)d_in[1];
    const float* benc = (const float*)d_in[2];
    const float* nul  = (const float*)d_in[3];
    const float* thl  = (const float*)d_in[4];
    const float* Bre  = (const float*)d_in[5];
    const float* Bim  = (const float*)d_in[6];
    const float* Cre  = (const float*)d_in[7];
    const float* Cim  = (const float*)d_in[8];
    const float* Dd   = (const float*)d_in[9];
    const float* W1   = (const float*)d_in[10];
    const float* b1   = (const float*)d_in[11];
    const float* W2   = (const float*)d_in[12];
    const float* b2   = (const float*)d_in[13];
    const float* bns  = (const float*)d_in[14];
    const float* bnb  = (const float*)d_in[15];
    const float* Wout = (const float*)d_in[16];
    const float* bout = (const float*)d_in[17];

    dim3 g2(512, 2), g4(512, 4), g8(512, 8);

    // encoder: y = x @ W_enc + b_enc   (writes g_y + BN partials)
    gemm_nn<0><<<g2, 256>>>(x, 64, Wenc, benc);

    int xsel = 0;
    for (int i = 0; i < NBLK; i++) {
        bn_lam<<<257, 256>>>(bns + i * 256, bnb + i * 256, nul + i * 256, thl + i * 256);
        gemm_bu2<<<g4, 256>>>(xsel, Bre + (size_t)i * 65536, Bim + (size_t)i * 65536);
        scan_final4<<<BB * 4, 256>>>();
        gemm_cproj<<<g2, 256>>>(Cre + (size_t)i * 65536, Cim + (size_t)i * 65536,
                                Dd + i * 256, xsel);
        gemm_glu<<<g8, 256>>>(W1 + (size_t)i * 256 * 1024, b1 + i * 1024);
        gemm_nn<1><<<g2, 256>>>(nullptr, 512, W2 + (size_t)i * 512 * 256, b2 + i * 256);
        xsel = 1;
    }
    pool_head<<<BB, 256>>>(Wout, bout, (float*)d_out);
}

// round 16
// speedup vs baseline: 1.0147x; 1.0147x over previous
#include <cuda_runtime.h>

// ---------------- problem constants ----------------
#define MTOT 65536
#define EF   256
#define HF   256
#define LF   1024
#define NBLK 6
#define TLEN 2048
#define BB   32
#define NC   32          // scan chunks of 64
#define TC   64

// ---------------- scratch (device globals) ----------------
static __device__ float g_y[(size_t)MTOT * EF];
static __device__ float g_x[(size_t)MTOT * EF];
static __device__ float g_bure[(size_t)MTOT * HF];
static __device__ float g_buim[(size_t)MTOT * HF];
static __device__ float g_hre[(size_t)MTOT * HF];
static __device__ float g_him[(size_t)MTOT * HF];
static __device__ float g_u[(size_t)MTOT * EF];
static __device__ float g_g[(size_t)MTOT * (LF / 2)];
static __device__ float g_part[512 * 512];
static __device__ float g_bna[EF], g_bnc[EF];
static __device__ float g_lr[HF], g_li[HF], g_gam[HF];
static __device__ float g_l8r[HF], g_l8i[HF];
static __device__ float g_L64r[HF], g_L64i[HF];
static __device__ float g_car_re[BB * NC * HF], g_car_im[BB * NC * HF];

// ======== fused BN finalize (blocks 0..255) + lambda precompute (block 256) ========
__global__ void __launch_bounds__(256) bn_lam(const float* __restrict__ scale,
                                              const float* __restrict__ bias,
                                              const float* __restrict__ nul,
                                              const float* __restrict__ thl) {
    if (blockIdx.x == 256) {
        int h = threadIdx.x;
        float nu = expf(nul[h]);
        float th = expf(thl[h]);
        float r = expf(-nu);
        float sn, cs;
        sincosf(th, &sn, &cs);
        float lr = r * cs, li = r * sn;
        g_lr[h] = lr;
        g_li[h] = li;
        g_gam[h] = sqrtf(fmaxf(1.0f - r * r, 1e-12f));
        float ar = lr, ai = li;
#pragma unroll
        for (int s = 0; s < 3; s++) {        // lam^8
            float nr = ar * ar - ai * ai;
            float ni = 2.0f * ar * ai;
            ar = nr;
            ai = ni;
        }
        g_l8r[h] = ar;
        g_l8i[h] = ai;
#pragma unroll
        for (int s = 0; s < 3; s++) {        // lam^64
            float nr = ar * ar - ai * ai;
            float ni = 2.0f * ar * ai;
            ar = nr;
            ai = ni;
        }
        g_L64r[h] = ar;
        g_L64i[h] = ai;
        return;
    }
    __shared__ float sm1[256], sm2[256];
    int e = blockIdx.x;
    int t = threadIdx.x;
    float s = g_part[t * 512 + e] + g_part[(t + 256) * 512 + e];
    float s2 = g_part[t * 512 + 256 + e] + g_part[(t + 256) * 512 + 256 + e];
    sm1[t] = s;
    sm2[t] = s2;
    __syncthreads();
    for (int st = 128; st > 0; st >>= 1) {
        if (t < st) {
            sm1[t] += sm1[t + st];
            sm2[t] += sm2[t + st];
        }
        __syncthreads();
    }
    if (t == 0) {
        const float inv = 1.0f / 65536.0f;
        float mu = sm1[0] * inv;
        float var = fmaxf(sm2[0] * inv - mu * mu, 0.0f);
        float a = rsqrtf(var + 1e-5f) * scale[e];
        g_bna[e] = a;
        g_bnc[e] = bias[e] - mu * a;
    }
}

// ================= GEMM: (bure,buim) = BN(x) @ [Bre^T, Bim^T] * gamma  (fused dual-B TN)
//   KC=16 champion; epilogue emits TWO 64-row chunk carries per CTA ====================
__global__ void __launch_bounds__(256) gemm_bu2(int xsel, const float* __restrict__ Wr,
                                                const float* __restrict__ Wi) {
    const float* A = xsel ? g_x : g_y;
    __shared__ __align__(16) float As[16][128];
    __shared__ __align__(16) float Bsr[16][64];
    __shared__ __align__(16) float Bsi[16][64];
    const int tid = threadIdx.x;
    const int m0 = blockIdx.x * 128;
    const int n0 = blockIdx.y * 64;
    const int tx = tid & 15;
    const int ty = tid >> 4;
    const int lr = tid >> 2;
    const int lk = (tid & 3) * 4;
    float accr[8][4], acci[8][4];
#pragma unroll
    for (int j = 0; j < 8; j++)
#pragma unroll
        for (int i = 0; i < 4; i++) { accr[j][i] = 0.f; acci[j][i] = 0.f; }

    for (int k0 = 0; k0 < 256; k0 += 16) {
        float4 a0 = *(const float4*)(A + (size_t)(m0 + lr) * 256 + k0 + lk);
        float4 a1 = *(const float4*)(A + (size_t)(m0 + lr + 64) * 256 + k0 + lk);
        float4 wr = *(const float4*)(Wr + (size_t)(n0 + lr) * 256 + k0 + lk);
        float4 wi = *(const float4*)(Wi + (size_t)(n0 + lr) * 256 + k0 + lk);
        float4 ba = *(const float4*)(g_bna + k0 + lk);
        float4 bc = *(const float4*)(g_bnc + k0 + lk);
        a0.x = fmaf(ba.x, a0.x, bc.x); a0.y = fmaf(ba.y, a0.y, bc.y);
        a0.z = fmaf(ba.z, a0.z, bc.z); a0.w = fmaf(ba.w, a0.w, bc.w);
        a1.x = fmaf(ba.x, a1.x, bc.x); a1.y = fmaf(ba.y, a1.y, bc.y);
        a1.z = fmaf(ba.z, a1.z, bc.z); a1.w = fmaf(ba.w, a1.w, bc.w);
        __syncthreads();
        As[lk + 0][lr] = a0.x; As[lk + 1][lr] = a0.y; As[lk + 2][lr] = a0.z; As[lk + 3][lr] = a0.w;
        As[lk + 0][lr + 64] = a1.x; As[lk + 1][lr + 64] = a1.y;
        As[lk + 2][lr + 64] = a1.z; As[lk + 3][lr + 64] = a1.w;
        Bsr[lk + 0][lr] = wr.x; Bsr[lk + 1][lr] = wr.y; Bsr[lk + 2][lr] = wr.z; Bsr[lk + 3][lr] = wr.w;
        Bsi[lk + 0][lr] = wi.x; Bsi[lk + 1][lr] = wi.y; Bsi[lk + 2][lr] = wi.z; Bsi[lk + 3][lr] = wi.w;
        __syncthreads();
#pragma unroll
        for (int kk = 0; kk < 16; kk++) {
            float4 av0 = *(const float4*)&As[kk][ty * 8];
            float4 av1 = *(const float4*)&As[kk][ty * 8 + 4];
            float4 br = *(const float4*)&Bsr[kk][tx * 4];
            float4 bi = *(const float4*)&Bsi[kk][tx * 4];
            float a[8] = {av0.x, av0.y, av0.z, av0.w, av1.x, av1.y, av1.z, av1.w};
            float brv[4] = {br.x, br.y, br.z, br.w};
            float biv[4] = {bi.x, bi.y, bi.z, bi.w};
#pragma unroll
            for (int j = 0; j < 8; j++)
#pragma unroll
                for (int i = 0; i < 4; i++) {
                    accr[j][i] = fmaf(a[j], brv[i], accr[j][i]);
                    acci[j][i] = fmaf(a[j], biv[i], acci[j][i]);
                }
        }
    }
    float4 gm = *(const float4*)(g_gam + n0 + tx * 4);
    float sr[4] = {0.f, 0.f, 0.f, 0.f}, si[4] = {0.f, 0.f, 0.f, 0.f};
    float lrv[4], liv[4];
#pragma unroll
    for (int i = 0; i < 4; i++) {
        lrv[i] = g_lr[n0 + tx * 4 + i];
        liv[i] = g_li[n0 + tx * 4 + i];
    }
#pragma unroll
    for (int j = 0; j < 8; j++) {
        size_t row = (size_t)(m0 + ty * 8 + j);
        float ur[4], ui[4];
        ur[0] = accr[j][0] * gm.x; ur[1] = accr[j][1] * gm.y;
        ur[2] = accr[j][2] * gm.z; ur[3] = accr[j][3] * gm.w;
        ui[0] = acci[j][0] * gm.x; ui[1] = acci[j][1] * gm.y;
        ui[2] = acci[j][2] * gm.z; ui[3] = acci[j][3] * gm.w;
        *(float4*)(g_bure + row * 256 + n0 + tx * 4) = make_float4(ur[0], ur[1], ur[2], ur[3]);
        *(float4*)(g_buim + row * 256 + n0 + tx * 4) = make_float4(ui[0], ui[1], ui[2], ui[3]);
#pragma unroll
        for (int i = 0; i < 4; i++) {
            float nr = fmaf(lrv[i], sr[i], fmaf(-liv[i], si[i], ur[i]));
            float ni = fmaf(lrv[i], si[i], fmaf(liv[i], sr[i], ui[i]));
            sr[i] = nr;
            si[i] = ni;
        }
    }
    __syncthreads();
#pragma unroll
    for (int i = 0; i < 4; i++) {
        As[ty][tx * 4 + i] = sr[i];
        As[ty][64 + tx * 4 + i] = si[i];
    }
    __syncthreads();
    if (tid < 64) {
        int col = tid;
        int n = n0 + col;
        float l8r = g_l8r[n], l8i = g_l8i[n];
        int b = m0 >> 11;
        int cchA = (m0 >> 6) & 31;      // chunk of rows [m0, m0+64)
        // carry A: groups 0..7 (rows 0..63), from zero
        float Hr = 0.f, Hi = 0.f;
#pragma unroll
        for (int gI = 0; gI < 8; gI++) {
            float ur = As[gI][col], ui = As[gI][64 + col];
            float nr = fmaf(l8r, Hr, fmaf(-l8i, Hi, ur));
            float ni = fmaf(l8r, Hi, fmaf(l8i, Hr, ui));
            Hr = nr;
            Hi = ni;
        }
        g_car_re[(b * NC + cchA) * HF + n] = Hr;
        g_car_im[(b * NC + cchA) * HF + n] = Hi;
        // carry B: groups 8..15 (rows 64..127), from zero
        Hr = 0.f;
        Hi = 0.f;
#pragma unroll
        for (int gI = 8; gI < 16; gI++) {
            float ur = As[gI][col], ui = As[gI][64 + col];
            float nr = fmaf(l8r, Hr, fmaf(-l8i, Hi, ur));
            float ni = fmaf(l8r, Hi, fmaf(l8i, Hr, ui));
            Hr = nr;
            Hi = ni;
        }
        g_car_re[(b * NC + cchA + 1) * HF + n] = Hr;
        g_car_im[(b * NC + cchA + 1) * HF + n] = Hi;
    }
}

// ===== scan final: 4 h-cols/thread (float4), TC=64, prefix recompute with lam^64 ========
__global__ void __launch_bounds__(256) scan_final4() {
    const int tid = threadIdx.x;
    const int hq = (tid & 63) * 4;
    const int cloc = tid >> 6;              // 0..3
    const int b = blockIdx.x >> 3;
    const int c = (blockIdx.x & 7) * 4 + cloc;
    float4 lr4 = *(const float4*)(g_lr + hq);
    float4 li4 = *(const float4*)(g_li + hq);
    float4 Lr4 = *(const float4*)(g_L64r + hq);
    float4 Li4 = *(const float4*)(g_L64i + hq);
    float lr[4] = {lr4.x, lr4.y, lr4.z, lr4.w};
    float li[4] = {li4.x, li4.y, li4.z, li4.w};
    float Lr[4] = {Lr4.x, Lr4.y, Lr4.z, Lr4.w};
    float Li[4] = {Li4.x, Li4.y, Li4.z, Li4.w};
    float hr[4] = {0.f, 0.f, 0.f, 0.f}, hi[4] = {0.f, 0.f, 0.f, 0.f};
    for (int j = 0; j < c; j++) {
        const float4 cr4 = *(const float4*)(g_car_re + (b * NC + j) * HF + hq);
        const float4 ci4 = *(const float4*)(g_car_im + (b * NC + j) * HF + hq);
        float cr[4] = {cr4.x, cr4.y, cr4.z, cr4.w};
        float ci[4] = {ci4.x, ci4.y, ci4.z, ci4.w};
#pragma unroll
        for (int i = 0; i < 4; i++) {
            float nr = fmaf(Lr[i], hr[i], fmaf(-Li[i], hi[i], cr[i]));
            float ni = fmaf(Lr[i], hi[i], fmaf(Li[i], hr[i], ci[i]));
            hr[i] = nr;
            hi[i] = ni;
        }
    }
    size_t base = ((size_t)b * TLEN + c * TC) * HF + hq;
#pragma unroll 2
    for (int t = 0; t < TC; t++) {
        size_t idx = base + (size_t)t * HF;
        float4 ur4 = *(const float4*)(g_bure + idx);
        float4 ui4 = *(const float4*)(g_buim + idx);
        float ur[4] = {ur4.x, ur4.y, ur4.z, ur4.w};
        float ui[4] = {ui4.x, ui4.y, ui4.z, ui4.w};
#pragma unroll
        for (int i = 0; i < 4; i++) {
            float nr = fmaf(lr[i], hr[i], fmaf(-li[i], hi[i], ur[i]));
            float ni = fmaf(lr[i], hi[i], fmaf(li[i], hr[i], ui[i]));
            hr[i] = nr;
            hi[i] = ni;
        }
        *(float4*)(g_hre + idx) = make_float4(hr[0], hr[1], hr[2], hr[3]);
        *(float4*)(g_him + idx) = make_float4(hi[0], hi[1], hi[2], hi[3]);
    }
}

// ================= GEMM: u = Re(hs @ Cc) + D*BN(x)  (dual TN, wide N=128, KC=16) =========
__global__ void __launch_bounds__(256) gemm_cproj(const float* __restrict__ Wr,
                                                  const float* __restrict__ Wi,
                                                  const float* __restrict__ Dv, int xsel) {
    const float* Xin = xsel ? g_x : g_y;
    __shared__ __align__(16) float Asr[16][128];
    __shared__ __align__(16) float Asi[16][128];
    __shared__ __align__(16) float Bsr[16][128];
    __shared__ __align__(16) float Bsi[16][128];
    const int tid = threadIdx.x;
    const int m0 = blockIdx.x * 128;
    const int n0 = blockIdx.y * 128;
    const int tx = tid & 15;
    const int ty = tid >> 4;
    const int lr = tid >> 2;
    const int lk = (tid & 3) * 4;
    float acc[8][2][4];
#pragma unroll
    for (int j = 0; j < 8; j++)
#pragma unroll
        for (int g = 0; g < 2; g++)
#pragma unroll
            for (int i = 0; i < 4; i++) acc[j][g][i] = 0.f;

    for (int k0 = 0; k0 < 256; k0 += 16) {
        float4 ar0 = *(const float4*)(g_hre + (size_t)(m0 + lr) * 256 + k0 + lk);
        float4 ar1 = *(const float4*)(g_hre + (size_t)(m0 + lr + 64) * 256 + k0 + lk);
        float4 ai0 = *(const float4*)(g_him + (size_t)(m0 + lr) * 256 + k0 + lk);
        float4 ai1 = *(const float4*)(g_him + (size_t)(m0 + lr + 64) * 256 + k0 + lk);
        float4 wr0 = *(const float4*)(Wr + (size_t)(n0 + lr) * 256 + k0 + lk);
        float4 wr1 = *(const float4*)(Wr + (size_t)(n0 + lr + 64) * 256 + k0 + lk);
        float4 wi0 = *(const float4*)(Wi + (size_t)(n0 + lr) * 256 + k0 + lk);
        float4 wi1 = *(const float4*)(Wi + (size_t)(n0 + lr + 64) * 256 + k0 + lk);
        __syncthreads();
        Asr[lk + 0][lr] = ar0.x; Asr[lk + 1][lr] = ar0.y; Asr[lk + 2][lr] = ar0.z; Asr[lk + 3][lr] = ar0.w;
        Asr[lk + 0][lr + 64] = ar1.x; Asr[lk + 1][lr + 64] = ar1.y;
        Asr[lk + 2][lr + 64] = ar1.z; Asr[lk + 3][lr + 64] = ar1.w;
        Asi[lk + 0][lr] = ai0.x; Asi[lk + 1][lr] = ai0.y; Asi[lk + 2][lr] = ai0.z; Asi[lk + 3][lr] = ai0.w;
        Asi[lk + 0][lr + 64] = ai1.x; Asi[lk + 1][lr + 64] = ai1.y;
        Asi[lk + 2][lr + 64] = ai1.z; Asi[lk + 3][lr + 64] = ai1.w;
        Bsr[lk + 0][lr] = wr0.x; Bsr[lk + 1][lr] = wr0.y; Bsr[lk + 2][lr] = wr0.z; Bsr[lk + 3][lr] = wr0.w;
        Bsr[lk + 0][lr + 64] = wr1.x; Bsr[lk + 1][lr + 64] = wr1.y;
        Bsr[lk + 2][lr + 64] = wr1.z; Bsr[lk + 3][lr + 64] = wr1.w;
        Bsi[lk + 0][lr] = wi0.x; Bsi[lk + 1][lr] = wi0.y; Bsi[lk + 2][lr] = wi0.z; Bsi[lk + 3][lr] = wi0.w;
        Bsi[lk + 0][lr + 64] = wi1.x; Bsi[lk + 1][lr + 64] = wi1.y;
        Bsi[lk + 2][lr + 64] = wi1.z; Bsi[lk + 3][lr + 64] = wi1.w;
        __syncthreads();
#pragma unroll
        for (int kk = 0; kk < 16; kk++) {
            float4 r0 = *(const float4*)&Asr[kk][ty * 8];
            float4 r1 = *(const float4*)&Asr[kk][ty * 8 + 4];
            float4 i0 = *(const float4*)&Asi[kk][ty * 8];
            float4 i1 = *(const float4*)&Asi[kk][ty * 8 + 4];
            float4 br0 = *(const float4*)&Bsr[kk][tx * 4];
            float4 br1 = *(const float4*)&Bsr[kk][tx * 4 + 64];
            float4 bi0 = *(const float4*)&Bsi[kk][tx * 4];
            float4 bi1 = *(const float4*)&Bsi[kk][tx * 4 + 64];
            float arv[8] = {r0.x, r0.y, r0.z, r0.w, r1.x, r1.y, r1.z, r1.w};
            float aiv[8] = {i0.x, i0.y, i0.z, i0.w, i1.x, i1.y, i1.z, i1.w};
            float brv[2][4] = {{br0.x, br0.y, br0.z, br0.w}, {br1.x, br1.y, br1.z, br1.w}};
            float biv[2][4] = {{bi0.x, bi0.y, bi0.z, bi0.w}, {bi1.x, bi1.y, bi1.z, bi1.w}};
#pragma unroll
            for (int j = 0; j < 8; j++)
#pragma unroll
                for (int g = 0; g < 2; g++)
#pragma unroll
                    for (int i = 0; i < 4; i++) {
                        acc[j][g][i] = fmaf(arv[j], brv[g][i], acc[j][g][i]);
                        acc[j][g][i] = fmaf(-aiv[j], biv[g][i], acc[j][g][i]);
                    }
        }
    }
#pragma unroll
    for (int g = 0; g < 2; g++) {
        int n = n0 + g * 64 + tx * 4;
        float4 dq = *(const float4*)(Dv + n);
        float4 ba = *(const float4*)(g_bna + n);
        float4 bc = *(const float4*)(g_bnc + n);
#pragma unroll
        for (int j = 0; j < 8; j++) {
            size_t row = (size_t)(m0 + ty * 8 + j);
            float4 xv = *(const float4*)(Xin + row * 256 + n);
            float4 o;
            o.x = acc[j][g][0] + dq.x * fmaf(ba.x, xv.x, bc.x);
            o.y = acc[j][g][1] + dq.y * fmaf(ba.y, xv.y, bc.y);
            o.z = acc[j][g][2] + dq.z * fmaf(ba.z, xv.z, bc.z);
            o.w = acc[j][g][3] + dq.w * fmaf(ba.w, xv.w, bc.w);
            *(float4*)(g_u + row * 256 + n) = o;
        }
    }
}

// ================= GEMM: g = GLU(u @ W1 + b1)   (NN, dual-B tile, KC=16) =================
__global__ void __launch_bounds__(256) gemm_glu(const float* __restrict__ W1,
                                                const float* __restrict__ b1) {
    __shared__ __align__(16) float As[16][128];
    __shared__ __align__(16) float Ba[16][64];
    __shared__ __align__(16) float Bb[16][64];
    const int tid = threadIdx.x;
    const int m0 = blockIdx.x * 128;
    const int n0 = blockIdx.y * 64;
    const int tx = tid & 15;
    const int ty = tid >> 4;
    const int lr = tid >> 2;
    const int lk = (tid & 3) * 4;
    const int bk = tid >> 4;
    const int bn = (tid & 15) * 4;
    float acca[8][4], accb[8][4];
#pragma unroll
    for (int j = 0; j < 8; j++)
#pragma unroll
        for (int i = 0; i < 4; i++) { acca[j][i] = 0.f; accb[j][i] = 0.f; }

    for (int k0 = 0; k0 < 256; k0 += 16) {
        float4 a0 = *(const float4*)(g_u + (size_t)(m0 + lr) * 256 + k0 + lk);
        float4 a1 = *(const float4*)(g_u + (size_t)(m0 + lr + 64) * 256 + k0 + lk);
        float4 wa = *(const float4*)(W1 + (size_t)(k0 + bk) * 1024 + n0 + bn);
        float4 wb = *(const float4*)(W1 + (size_t)(k0 + bk) * 1024 + 512 + n0 + bn);
        __syncthreads();
        As[lk + 0][lr] = a0.x; As[lk + 1][lr] = a0.y; As[lk + 2][lr] = a0.z; As[lk + 3][lr] = a0.w;
        As[lk + 0][lr + 64] = a1.x; As[lk + 1][lr + 64] = a1.y;
        As[lk + 2][lr + 64] = a1.z; As[lk + 3][lr + 64] = a1.w;
        *(float4*)&Ba[bk][bn] = wa;
        *(float4*)&Bb[bk][bn] = wb;
        __syncthreads();
#pragma unroll
        for (int kk = 0; kk < 16; kk++) {
            float4 av0 = *(const float4*)&As[kk][ty * 8];
            float4 av1 = *(const float4*)&As[kk][ty * 8 + 4];
            float4 bva = *(const float4*)&Ba[kk][tx * 4];
            float4 bvb = *(const float4*)&Bb[kk][tx * 4];
            float a[8] = {av0.x, av0.y, av0.z, av0.w, av1.x, av1.y, av1.z, av1.w};
            float ba_[4] = {bva.x, bva.y, bva.z, bva.w};
            float bb_[4] = {bvb.x, bvb.y, bvb.z, bvb.w};
#pragma unroll
            for (int j = 0; j < 8; j++)
#pragma unroll
                for (int i = 0; i < 4; i++) {
                    acca[j][i] = fmaf(a[j], ba_[i], acca[j][i]);
                    accb[j][i] = fmaf(a[j], bb_[i], accb[j][i]);
                }
        }
    }
    float4 b1a = *(const float4*)(b1 + n0 + tx * 4);
    float4 b1b = *(const float4*)(b1 + 512 + n0 + tx * 4);
#pragma unroll
    for (int j = 0; j < 8; j++) {
        float za[4], zb[4];
        za[0] = acca[j][0] + b1a.x; za[1] = acca[j][1] + b1a.y;
        za[2] = acca[j][2] + b1a.z; za[3] = acca[j][3] + b1a.w;
        zb[0] = accb[j][0] + b1b.x; zb[1] = accb[j][1] + b1b.y;
        zb[2] = accb[j][2] + b1b.z; zb[3] = accb[j][3] + b1b.w;
        float4 o;
        o.x = __fdividef(za[0], 1.0f + __expf(-zb[0]));
        o.y = __fdividef(za[1], 1.0f + __expf(-zb[1]));
        o.z = __fdividef(za[2], 1.0f + __expf(-zb[2]));
        o.w = __fdividef(za[3], 1.0f + __expf(-zb[3]));
        *(float4*)(g_g + (size_t)(m0 + ty * 8 + j) * 512 + n0 + tx * 4) = o;
    }
}

// ================= GEMM NN wide (encoder ROLE=0, MLP2+residual ROLE=1; N=128, KC=16) =====
template <int ROLE>
__global__ void __launch_bounds__(256) gemm_nn(const float* __restrict__ Aext, int K,
                                               const float* __restrict__ B,
                                               const float* __restrict__ bias) {
    const float* A = (ROLE == 0) ? Aext : g_g;
    float* out = (ROLE == 0) ? g_y : g_x;
    __shared__ __align__(16) float As[16][128];
    __shared__ __align__(16) float Bs[16][128];
    const int tid = threadIdx.x;
    const int m0 = blockIdx.x * 128;
    const int n0 = blockIdx.y * 128;
    const int tx = tid & 15;
    const int ty = tid >> 4;
    const int lr = tid >> 2;
    const int lk = (tid & 3) * 4;
    const int bk = tid >> 4;
    const int bn = (tid & 15) * 4;
    float acc[8][2][4];
#pragma unroll
    for (int j = 0; j < 8; j++)
#pragma unroll
        for (int g = 0; g < 2; g++)
#pragma unroll
            for (int i = 0; i < 4; i++) acc[j][g][i] = 0.f;

    for (int k0 = 0; k0 < K; k0 += 16) {
        float4 a0 = *(const float4*)(A + (size_t)(m0 + lr) * K + k0 + lk);
        float4 a1 = *(const float4*)(A + (size_t)(m0 + lr + 64) * K + k0 + lk);
        float4 wv0 = *(const float4*)(B + (size_t)(k0 + bk) * 256 + n0 + bn);
        float4 wv1 = *(const float4*)(B + (size_t)(k0 + bk) * 256 + n0 + 64 + bn);
        __syncthreads();
        As[lk + 0][lr] = a0.x; As[lk + 1][lr] = a0.y; As[lk + 2][lr] = a0.z; As[lk + 3][lr] = a0.w;
        As[lk + 0][lr + 64] = a1.x; As[lk + 1][lr + 64] = a1.y;
        As[lk + 2][lr + 64] = a1.z; As[lk + 3][lr + 64] = a1.w;
        *(float4*)&Bs[bk][bn] = wv0;
        *(float4*)&Bs[bk][bn + 64] = wv1;
        __syncthreads();
#pragma unroll
        for (int kk = 0; kk < 16; kk++) {
            float4 av0 = *(const float4*)&As[kk][ty * 8];
            float4 av1 = *(const float4*)&As[kk][ty * 8 + 4];
            float4 bv0 = *(const float4*)&Bs[kk][tx * 4];
            float4 bv1 = *(const float4*)&Bs[kk][tx * 4 + 64];
            float a[8] = {av0.x, av0.y, av0.z, av0.w, av1.x, av1.y, av1.z, av1.w};
            float bv[2][4] = {{bv0.x, bv0.y, bv0.z, bv0.w}, {bv1.x, bv1.y, bv1.z, bv1.w}};
#pragma unroll
            for (int j = 0; j < 8; j++)
#pragma unroll
                for (int g = 0; g < 2; g++)
#pragma unroll
                    for (int i = 0; i < 4; i++)
                        acc[j][g][i] = fmaf(a[j], bv[g][i], acc[j][g][i]);
        }
    }

    float ls[2][4], ls2[2][4];
#pragma unroll
    for (int g = 0; g < 2; g++)
#pragma unroll
        for (int i = 0; i < 4; i++) { ls[g][i] = 0.f; ls2[g][i] = 0.f; }
#pragma unroll
    for (int g = 0; g < 2; g++) {
        int n = n0 + g * 64 + tx * 4;
        float4 bq = *(const float4*)(bias + n);
#pragma unroll
        for (int j = 0; j < 8; j++) {
            size_t row = (size_t)(m0 + ty * 8 + j);
            float4 o;
            o.x = acc[j][g][0] + bq.x; o.y = acc[j][g][1] + bq.y;
            o.z = acc[j][g][2] + bq.z; o.w = acc[j][g][3] + bq.w;
            if (ROLE == 1) {
                float4 yv = *(const float4*)(g_y + row * 256 + n);
                o.x += yv.x; o.y += yv.y; o.z += yv.z; o.w += yv.w;
            }
            ls[g][0] += o.x; ls[g][1] += o.y; ls[g][2] += o.z; ls[g][3] += o.w;
            ls2[g][0] += o.x * o.x; ls2[g][1] += o.y * o.y;
            ls2[g][2] += o.z * o.z; ls2[g][3] += o.w * o.w;
            *(float4*)(out + row * 256 + n) = o;
        }
    }

    float* red = &As[0][0];
    __syncthreads();
#pragma unroll
    for (int g = 0; g < 2; g++)
#pragma unroll
        for (int i = 0; i < 4; i++) red[tid * 8 + g * 4 + i] = ls[g][i];
    __syncthreads();
    float sv = 0.f;
    if (tid < 128) {
        int g = tid >> 6, txr = (tid >> 2) & 15, ir = tid & 3;
#pragma unroll
        for (int k = 0; k < 16; k++) sv += red[(k * 16 + txr) * 8 + g * 4 + ir];
    }
    __syncthreads();
#pragma unroll
    for (int g = 0; g < 2; g++)
#pragma unroll
        for (int i = 0; i < 4; i++) red[tid * 8 + g * 4 + i] = ls2[g][i];
    __syncthreads();
    if (tid < 128) {
        int g = tid >> 6, txr = (tid >> 2) & 15, ir = tid & 3;
        float s2 = 0.f;
#pragma unroll
        for (int k = 0; k < 16; k++) s2 += red[(k * 16 + txr) * 8 + g * 4 + ir];
        int col = n0 + g * 64 + txr * 4 + ir;
        g_part[blockIdx.x * 512 + col] = sv;
        g_part[blockIdx.x * 512 + 256 + col] = s2;
    }
}

// ================= fused mean-pool + head =================
__global__ void __launch_bounds__(256) pool_head(const float* __restrict__ Wout,
                                                 const float* __restrict__ bout,
                                                 float* __restrict__ out) {
    __shared__ float pooled[256];
    int b = blockIdx.x;
    int e = threadIdx.x;
    float s = 0.f;
#pragma unroll
    for (int k = 0; k < 16; k++) s += g_part[(b * 16 + k) * 512 + e];
    pooled[e] = s * (1.0f / (float)TLEN);
    __syncthreads();
    if (e < 10) {
        float acc = bout[e];
        for (int q = 0; q < 256; q++) acc = fmaf(pooled[q], Wout[q * 10 + e], acc);
        out[b * 10 + e] = acc;
    }
}

// ================= host orchestration =================
extern "C" void kernel_launch(void* const* d_in, const int* in_sizes, int n_in,
                              void* d_out, int out_size) {
    const float* x    = (const float*)d_in[0];
    const float* Wenc = (const float*)d_in[1];
    const float* benc = (const float*)d_in[2];
    const float* nul  = (const float*)d_in[3];
    const float* thl  = (const float*)d_in[4];
    const float* Bre  = (const float*)d_in[5];
    const float* Bim  = (const float*)d_in[6];
    const float* Cre  = (const float*)d_in[7];
    const float* Cim  = (const float*)d_in[8];
    const float* Dd   = (const float*)d_in[9];
    const float* W1   = (const float*)d_in[10];
    const float* b1   = (const float*)d_in[11];
    const float* W2   = (const float*)d_in[12];
    const float* b2   = (const float*)d_in[13];
    const float* bns  = (const float*)d_in[14];
    const float* bnb  = (const float*)d_in[15];
    const float* Wout = (const float*)d_in[16];
    const float* bout = (const float*)d_in[17];

    dim3 g2(512, 2), g4(512, 4), g8(512, 8);

    // encoder: y = x @ W_enc + b_enc   (writes g_y + BN partials)
    gemm_nn<0><<<g2, 256>>>(x, 64, Wenc, benc);

    int xsel = 0;
    for (int i = 0; i < NBLK; i++) {
        bn_lam<<<257, 256>>>(bns + i * 256, bnb + i * 256, nul + i * 256, thl + i * 256);
        gemm_bu2<<<g4, 256>>>(xsel, Bre + (size_t)i * 65536, Bim + (size_t)i * 65536);
        scan_final4<<<BB * 8, 256>>>();
        gemm_cproj<<<g2, 256>>>(Cre + (size_t)i * 65536, Cim + (size_t)i * 65536,
                                Dd + i * 256, xsel);
        gemm_glu<<<g8, 256>>>(W1 + (size_t)i * 256 * 1024, b1 + i * 1024);
        gemm_nn<1><<<g2, 256>>>(nullptr, 512, W2 + (size_t)i * 512 * 256, b2 + i * 256);
        xsel = 1;
    }
    pool_head<<<BB, 256>>>(Wout, bout, (float*)d_out);
}